// round 2
// baseline (speedup 1.0000x reference)
#include <cuda_runtime.h>
#include <math.h>

#define HEADS   8
#define DFUSED  480
#define E_MAX   262144
#define NH_MAX  (16384 * HEADS)

// Scratch (no device allocation allowed -> __device__ globals)
__device__ float        g_w[(size_t)E_MAX * HEADS];   // logits, then exp(w-m)
__device__ unsigned int g_m[NH_MAX];                  // per (node,head) max (encoded)
__device__ float        g_s[NH_MAX];                  // per (node,head) sum
__device__ int          g_is64;                       // edge_index dtype flag

// Monotonic float<->uint encoding so atomicMax(uint) == max(float)
__device__ __forceinline__ unsigned int enc_f(float f) {
    unsigned int u = __float_as_uint(f);
    return (u & 0x80000000u) ? ~u : (u | 0x80000000u);
}
__device__ __forceinline__ float dec_f(unsigned int e) {
    return (e & 0x80000000u) ? __uint_as_float(e ^ 0x80000000u)
                             : __uint_as_float(~e);
}

// head of fused feature index j (block sizes 128/192/160; head strides 16/24/20)
__device__ __forceinline__ int head_of(int j) {
    return (j < 128) ? (j >> 4) : ((j < 320) ? (j - 128) / 24 : (j - 320) / 20);
}

// dtype-agnostic load of edge_index[1][e] (dst node), clamped to [0, N)
__device__ __forceinline__ int load_dst(const void* ei, int E, int e, int N) {
    int d;
    if (g_is64) d = (int)((const long long*)ei)[(size_t)E + e];
    else        d = ((const int*)ei)[E + e];
    d = d < 0 ? 0 : (d >= N ? N - 1 : d);
    return d;
}

// ---------------------------------------------------------------------------
// Kernel P: detect edge_index dtype. If underlying int64 (values < 2^31), the
// int32 view has zeros at every odd word. Reading 512 int32 words is in-bounds
// for both interpretations (2E >= 512).
// ---------------------------------------------------------------------------
__global__ void probe_kernel(const unsigned int* __restrict__ ei, int E) {
    __shared__ int nz;
    if (threadIdx.x == 0) nz = 0;
    __syncthreads();
    int lim = 2 * E < 512 ? 2 * E : 512;
    for (int i = threadIdx.x; i < lim; i += blockDim.x)
        if ((i & 1) && ei[i] != 0u) atomicAdd(&nz, 1);
    __syncthreads();
    if (threadIdx.x == 0) g_is64 = (nz == 0) ? 1 : 0;
}

// ---------------------------------------------------------------------------
// Kernel 0: init out=0, g_s=0, g_m=enc(minimum)
// ---------------------------------------------------------------------------
__global__ void init_kernel(float* __restrict__ out, int out_elems, int nh) {
    int stride = gridDim.x * blockDim.x;
    for (int i = blockIdx.x * blockDim.x + threadIdx.x; i < out_elems; i += stride)
        out[i] = 0.0f;
    for (int i = blockIdx.x * blockDim.x + threadIdx.x; i < nh; i += stride) {
        g_s[i] = 0.0f;
        g_m[i] = 0u;   // smallest encoded value
    }
}

// ---------------------------------------------------------------------------
// Kernel 1: per-edge per-head logits + segment max
// one warp per edge; float4 coalesced loads; per-head partials via smem atomics
// ---------------------------------------------------------------------------
__global__ void __launch_bounds__(256)
logits_kernel(const float* __restrict__ q, const float* __restrict__ k,
              const float* __restrict__ cutoff,
              const void* __restrict__ eidx, int E, int N) {
    __shared__ float sh[8][HEADS];            // 8 warps per block
    int e    = (blockIdx.x * blockDim.x + threadIdx.x) >> 5;
    int lane = threadIdx.x & 31;
    int wl   = threadIdx.x >> 5;
    if (e >= E) return;

    if (lane < HEADS) sh[wl][lane] = 0.0f;
    __syncwarp();

    const float4* q4 = (const float4*)(q + (size_t)e * DFUSED);
    const float4* k4 = (const float4*)(k + (size_t)e * DFUSED);

    // 480 floats = 120 float4
    #pragma unroll
    for (int t = 0; t < 4; t++) {
        int i4 = lane + 32 * t;
        if (i4 < 120) {
            float4 a = q4[i4];
            float4 b = k4[i4];
            float p = a.x * b.x + a.y * b.y + a.z * b.z + a.w * b.w;
            atomicAdd(&sh[wl][head_of(i4 * 4)], p);
        }
    }
    __syncwarp();

    if (lane < HEADS) {
        float wv = cutoff[e] * sh[wl][lane] * 0.12909944487358056f; // 1/sqrt(60)
        g_w[(size_t)e * HEADS + lane] = wv;
        int dst = load_dst(eidx, E, e, N);
        atomicMax(&g_m[dst * HEADS + lane], enc_f(wv));
    }
}

// ---------------------------------------------------------------------------
// Kernel 2: exp(w - m[dst]) and segment sum
// ---------------------------------------------------------------------------
__global__ void __launch_bounds__(256)
softmax_kernel(const void* __restrict__ eidx, int E, int N) {
    int tid = blockIdx.x * blockDim.x + threadIdx.x;
    if (tid >= E * HEADS) return;
    int e = tid >> 3;
    int h = tid & 7;
    int dst = load_dst(eidx, E, e, N);
    float m  = dec_f(g_m[dst * HEADS + h]);
    float ew = __expf(g_w[tid] - m);
    g_w[tid] = ew;
    atomicAdd(&g_s[dst * HEADS + h], ew);
}

// ---------------------------------------------------------------------------
// Kernel 3: normalized weighted scatter of values into out
// one warp per edge; float4 loads; red.global.add.v4.f32 (coalesced)
// ---------------------------------------------------------------------------
__global__ void __launch_bounds__(256)
scatter_kernel(const float* __restrict__ v, const void* __restrict__ eidx,
               float* __restrict__ out, int E, int N) {
    int e    = (blockIdx.x * blockDim.x + threadIdx.x) >> 5;
    int lane = threadIdx.x & 31;
    if (e >= E) return;

    int dst = load_dst(eidx, E, e, N);
    float coeff = 0.0f;
    if (lane < HEADS)
        coeff = g_w[(size_t)e * HEADS + lane] /
                (g_s[dst * HEADS + lane] + 1e-16f);

    const float4* v4 = (const float4*)(v + (size_t)e * DFUSED);
    float* oe = out + (size_t)dst * DFUSED;

    #pragma unroll
    for (int t = 0; t < 4; t++) {
        int i4 = lane + 32 * t;
        int j  = (i4 < 120) ? i4 * 4 : 476;            // clamp for safe head_of
        int h  = head_of(j);
        float c = __shfl_sync(0xffffffffu, coeff, h);  // warp fully converged
        if (i4 < 120) {
            float4 vv = v4[i4];
            float x = c * vv.x, y = c * vv.y, z = c * vv.z, w = c * vv.w;
            asm volatile("red.global.add.v4.f32 [%0], {%1, %2, %3, %4};"
                         :: "l"(oe + i4 * 4), "f"(x), "f"(y), "f"(z), "f"(w)
                         : "memory");
        }
    }
}

// ---------------------------------------------------------------------------
extern "C" void kernel_launch(void* const* d_in, const int* in_sizes, int n_in,
                              void* d_out, int out_size) {
    // Classify inputs by element count (robust to a scalar num_nodes input):
    //   3 buffers of size 480*E -> key, value, query (relative order preserved)
    //   1 buffer of size E      -> edge_weight_cutoff
    //   1 buffer of size 2*E    -> edge_index
    long long mx = 0;
    for (int i = 0; i < n_in; i++)
        if ((long long)in_sizes[i] > mx) mx = in_sizes[i];
    int E = (int)(mx / DFUSED);

    const float* big[3] = {0, 0, 0};
    const float* cutoff = 0;
    const void*  eidx   = 0;
    int nbig = 0;
    for (int i = 0; i < n_in; i++) {
        long long s = in_sizes[i];
        if (s == mx && nbig < 3)      big[nbig++] = (const float*)d_in[i];
        else if (s == (long long)E)   cutoff = (const float*)d_in[i];
        else if (s == 2LL * E)        eidx   = d_in[i];
    }
    const float* key   = big[0];
    const float* value = big[1];
    const float* query = big[2];

    int N = out_size / DFUSED;
    float* out = (float*)d_out;
    int nh = N * HEADS;

    probe_kernel<<<1, 256>>>((const unsigned int*)eidx, E);
    init_kernel<<<2048, 256>>>(out, out_size, nh);
    logits_kernel<<<(E + 7) / 8, 256>>>(query, key, cutoff, eidx, E, N);
    softmax_kernel<<<(E * HEADS + 255) / 256, 256>>>(eidx, E, N);
    scatter_kernel<<<(E + 7) / 8, 256>>>(value, eidx, out, E, N);
}

// round 3
// speedup vs baseline: 1.0916x; 1.0916x over previous
#include <cuda_runtime.h>
#include <math.h>

#define HEADS   8
#define DFUSED  480
#define NH_MAX  (16384 * HEADS)

// Scratch (no device allocation allowed -> __device__ globals)
__device__ float g_s[NH_MAX];   // per (node,head) sum of exp(w)
__device__ int   g_is64;        // edge_index dtype flag

// head of fused feature index j (block sizes 128/192/160; head strides 16/24/20)
__device__ __forceinline__ int head_of(int j) {
    return (j < 128) ? (j >> 4) : ((j < 320) ? (j - 128) / 24 : (j - 320) / 20);
}

// dtype-agnostic load of edge_index[1][e] (dst node), clamped to [0, N)
__device__ __forceinline__ int load_dst(const void* ei, int E, int e, int N) {
    int d;
    if (g_is64) d = (int)((const long long*)ei)[(size_t)E + e];
    else        d = ((const int*)ei)[E + e];
    d = d < 0 ? 0 : (d >= N ? N - 1 : d);
    return d;
}

// ---------------------------------------------------------------------------
// Kernel 0: init out=0, g_s=0; block 0 additionally probes edge_index dtype.
// If underlying int64 (all values < 2^31), the int32 view has zeros at every
// odd word. Reading 512 words is in-bounds for both interpretations.
// ---------------------------------------------------------------------------
__global__ void init_kernel(float* __restrict__ out, int out_elems, int nh,
                            const unsigned int* __restrict__ ei, int E) {
    if (blockIdx.x == 0) {
        __shared__ int nz;
        if (threadIdx.x == 0) nz = 0;
        __syncthreads();
        int lim = 2 * E < 512 ? 2 * E : 512;
        for (int i = threadIdx.x; i < lim; i += blockDim.x)
            if ((i & 1) && ei[i] != 0u) atomicAdd(&nz, 1);
        __syncthreads();
        if (threadIdx.x == 0) g_is64 = (nz == 0) ? 1 : 0;
    }
    int stride = gridDim.x * blockDim.x;
    for (int i = blockIdx.x * blockDim.x + threadIdx.x; i < out_elems; i += stride)
        out[i] = 0.0f;
    for (int i = blockIdx.x * blockDim.x + threadIdx.x; i < nh; i += stride)
        g_s[i] = 0.0f;
}

// ---------------------------------------------------------------------------
// Kernel 1 (fused): per edge — q.k dot per head, ew = exp(w), segment-sum ew,
// and scatter ew * v into out (unnormalized). One warp per edge.
// Softmax max-subtraction dropped: softmax is shift-invariant and logits here
// are O(5) (cutoff in [0,1], normalized q,k), so exp() cannot overflow.
// ---------------------------------------------------------------------------
__global__ void __launch_bounds__(256)
fused_edge_kernel(const float* __restrict__ q, const float* __restrict__ k,
                  const float* __restrict__ v, const float* __restrict__ cutoff,
                  const void* __restrict__ eidx,
                  float* __restrict__ out, int E, int N) {
    __shared__ float sh[8][HEADS];            // 8 warps per block
    int e    = (blockIdx.x * blockDim.x + threadIdx.x) >> 5;   // warp-uniform
    int lane = threadIdx.x & 31;
    int wl   = threadIdx.x >> 5;
    if (e >= E) return;

    if (lane < HEADS) sh[wl][lane] = 0.0f;
    __syncwarp();

    const float4* q4 = (const float4*)(q + (size_t)e * DFUSED);
    const float4* k4 = (const float4*)(k + (size_t)e * DFUSED);
    const float4* v4 = (const float4*)(v + (size_t)e * DFUSED);

    // q.k partial dots -> per-head smem accumulation (480 floats = 120 float4)
    #pragma unroll
    for (int t = 0; t < 4; t++) {
        int i4 = lane + 32 * t;
        if (i4 < 120) {
            float4 a = q4[i4];
            float4 b = k4[i4];
            float p = a.x * b.x + a.y * b.y + a.z * b.z + a.w * b.w;
            atomicAdd(&sh[wl][head_of(i4 * 4)], p);
        }
    }
    __syncwarp();

    int dst = load_dst(eidx, E, e, N);
    float ew = 0.0f;
    if (lane < HEADS) {
        float wv = cutoff[e] * sh[wl][lane] * 0.12909944487358056f; // 1/sqrt(60)
        ew = __expf(wv);
        atomicAdd(&g_s[dst * HEADS + lane], ew);
    }

    // scatter ew * v into out (coalesced vector reductions, all hit L2)
    float* oe = out + (size_t)dst * DFUSED;
    #pragma unroll
    for (int t = 0; t < 4; t++) {
        int i4 = lane + 32 * t;
        int j  = (i4 < 120) ? i4 * 4 : 476;            // clamp for safe head_of
        int h  = head_of(j);
        float c = __shfl_sync(0xffffffffu, ew, h);     // warp fully converged
        if (i4 < 120) {
            float4 vv = v4[i4];
            float x = c * vv.x, y = c * vv.y, z = c * vv.z, w = c * vv.w;
            asm volatile("red.global.add.v4.f32 [%0], {%1, %2, %3, %4};"
                         :: "l"(oe + i4 * 4), "f"(x), "f"(y), "f"(z), "f"(w)
                         : "memory");
        }
    }
}

// ---------------------------------------------------------------------------
// Kernel 2: normalize out by per-(node,head) sum. One thread per float4.
// ---------------------------------------------------------------------------
__global__ void __launch_bounds__(256)
normalize_kernel(float* __restrict__ out, int N) {
    int idx = blockIdx.x * blockDim.x + threadIdx.x;   // over N*120 float4s
    if (idx >= N * 120) return;
    int n  = idx / 120;
    int i4 = idx - n * 120;
    int h  = head_of(i4 * 4);
    float inv = 1.0f / (g_s[n * HEADS + h] + 1e-16f);
    float4* p = (float4*)(out + (size_t)n * DFUSED) + i4;
    float4 vv = *p;
    vv.x *= inv; vv.y *= inv; vv.z *= inv; vv.w *= inv;
    *p = vv;
}

// ---------------------------------------------------------------------------
extern "C" void kernel_launch(void* const* d_in, const int* in_sizes, int n_in,
                              void* d_out, int out_size) {
    // Classify inputs by element count (robust to scalar inputs):
    //   3 buffers of size 480*E -> key, value, query (relative order preserved)
    //   1 buffer of size E      -> edge_weight_cutoff
    //   1 buffer of size 2*E    -> edge_index
    long long mx = 0;
    for (int i = 0; i < n_in; i++)
        if ((long long)in_sizes[i] > mx) mx = in_sizes[i];
    int E = (int)(mx / DFUSED);

    const float* big[3] = {0, 0, 0};
    const float* cutoff = 0;
    const void*  eidx   = 0;
    int nbig = 0;
    for (int i = 0; i < n_in; i++) {
        long long s = in_sizes[i];
        if (s == mx && nbig < 3)      big[nbig++] = (const float*)d_in[i];
        else if (s == (long long)E)   cutoff = (const float*)d_in[i];
        else if (s == 2LL * E)        eidx   = d_in[i];
    }
    const float* key   = big[0];
    const float* value = big[1];
    const float* query = big[2];

    int N = out_size / DFUSED;
    float* out = (float*)d_out;
    int nh = N * HEADS;

    init_kernel<<<2048, 256>>>(out, out_size, nh, (const unsigned int*)eidx, E);
    fused_edge_kernel<<<(E + 7) / 8, 256>>>(query, key, value, cutoff, eidx,
                                            out, E, N);
    normalize_kernel<<<(N * 120 + 255) / 256, 256>>>(out, N);
}